// round 6
// baseline (speedup 1.0000x reference)
#include <cuda_runtime.h>
#include <cuda_fp16.h>
#include <cstdint>
#include <cstddef>

#define DEVI static __device__ __forceinline__

namespace li {

constexpr int B = 32, T = 1024, IN = 1024, OUT = 1024;
constexpr int TT = 128;                 // time rows per tile (GEMM M)
constexpr int TO = 128;                 // out cols per CTA   (GEMM N)
constexpr int BKH = 64;                 // halves per K slab (= one 128B row)
constexpr int SLABS = IN / BKH;         // 16
constexpr int TILES = T / TT;           // 8
constexpr int G = TILES * SLABS;        // 128 slabs per CTA

constexpr int STAGE_BYTES = (TT + TO) * 128;   // 32 KB (X 16K + W 16K, fp16)
constexpr int STG_STRIDE = 136;                // halves; conflict-free
constexpr int STAGING_OFF = 2 * STAGE_BYTES;   // 65536
constexpr int SMEM_DYN = STAGING_OFF + TT * STG_STRIDE * 2;  // 100352

__device__ __align__(16) __half g_Xh[(size_t)B * T * IN];   // 64MB scratch
__device__ __align__(16) __half g_Wh[(size_t)OUT * IN];     // 2MB scratch
__device__ int g_flags[TILES];
__device__ int g_cnt[TILES];

DEVI uint32_t s2u(const void* p) {
  uint32_t a;
  asm("{ .reg .u64 t; cvta.to.shared.u64 t, %1; cvt.u32.u64 %0, t; }"
      : "=r"(a) : "l"(p));
  return a;
}
DEVI void cp16(uint32_t s, const void* g) {
  asm volatile("cp.async.cg.shared.global [%0], [%1], 16;" :: "r"(s), "l"(g)
               : "memory");
}
DEVI void cp_commit() { asm volatile("cp.async.commit_group;" ::: "memory"); }
DEVI void cp_wait0() { asm volatile("cp.async.wait_group 0;" ::: "memory"); }

DEVI void ldsm4(uint32_t* r, uint32_t a) {
  asm volatile("ldmatrix.sync.aligned.m8n8.x4.shared.b16 {%0,%1,%2,%3}, [%4];"
               : "=r"(r[0]), "=r"(r[1]), "=r"(r[2]), "=r"(r[3]) : "r"(a));
}
DEVI void mma16(float* c, const uint32_t* a, const uint32_t* b) {
  asm volatile(
      "mma.sync.aligned.m16n8k16.row.col.f32.f16.f16.f32 "
      "{%0,%1,%2,%3}, {%4,%5,%6,%7}, {%8,%9}, {%0,%1,%2,%3};"
      : "+f"(c[0]), "+f"(c[1]), "+f"(c[2]), "+f"(c[3])
      : "r"(a[0]), "r"(a[1]), "r"(a[2]), "r"(a[3]), "r"(b[0]), "r"(b[1]));
}
DEVI uint32_t packh2(float lo, float hi) {
  uint32_t d;
  asm("cvt.rn.f16x2.f32 %0, %1, %2;" : "=r"(d) : "f"(hi), "f"(lo));
  return d;
}
DEVI int ld_acq(const int* p) {
  int v;
  asm volatile("ld.acquire.gpu.global.b32 %0, [%1];" : "=r"(v) : "l"(p));
  return v;
}
DEVI uint2 cvt2(float4 v) {
  __half2 a = __float22half2_rn({v.x, v.y});
  __half2 b = __float22half2_rn({v.z, v.w});
  uint2 u;
  u.x = *reinterpret_cast<unsigned*>(&a);
  u.y = *reinterpret_cast<unsigned*>(&b);
  return u;
}

// ---------------- flag reset (graph replays must re-run the pipeline) --------
__global__ void reset_kernel() {
  if (threadIdx.x < TILES) {
    g_flags[threadIdx.x] = 0;
    g_cnt[threadIdx.x] = 0;
  }
}

// ---------------- concurrent pre-pass: fp32 -> fp16, tile-by-tile ------------
__global__ void __launch_bounds__(256) cvt_kernel(const float4* __restrict__ X,
                                                  const float4* __restrict__ W) {
  const int nthr = gridDim.x * blockDim.x;
  const int t0 = blockIdx.x * blockDim.x + threadIdx.x;
  uint2* wo = reinterpret_cast<uint2*>(g_Wh);
  uint2* xo = reinterpret_cast<uint2*>(g_Xh);
  // weights first (needed by main's very first slab, gated by flag[0])
  for (int i = t0; i < OUT * IN / 4; i += nthr) wo[i] = cvt2(W[i]);
  // then X, one time-tile (across all batches) at a time
  const int per_bt = TT * IN / 4;  // 32768 float4 per (batch, tile)
  for (int tile = 0; tile < TILES; ++tile) {
    for (int i = t0; i < B * per_bt; i += nthr) {
      const int b = i >> 15;
      const int r = i & (per_bt - 1);
      const size_t src = (size_t)b * (T * IN / 4) + (size_t)tile * per_bt + r;
      xo[src] = cvt2(X[src]);
    }
    __syncthreads();
    if (threadIdx.x == 0) {
      __threadfence();
      const int prev = atomicAdd(&g_cnt[tile], 1);
      if (prev == (int)gridDim.x - 1) atomicExch(&g_flags[tile], 1);
    }
  }
}

// ---------------- main fused GEMM + leaky-integrator scan --------------------
// 128 threads, 4 warps in 2x2 grid, warp tile 64x64.
__global__ void __launch_bounds__(128, 2)
li_kernel(const float* __restrict__ bias, const float* __restrict__ decay,
          float* __restrict__ out) {
  extern __shared__ __align__(16) char dsm[];
  const uint32_t sbase = s2u(dsm);

  const int tid = threadIdx.x;
  const int wid = tid >> 5;
  const int lane = tid & 31;
  const int bb = blockIdx.x >> 3;
  const int o0 = (blockIdx.x & 7) * TO;

  // ---- scan state: every thread owns one o-channel ----
  const float dcy = decay[o0 + tid];
  const float omd = 1.0f - dcy;
  const float bo = bias[o0 + tid];
  float u = 0.f;

  // ---- cp.async constants: 16 chunks of 16B per thread ----
  const int lr = tid >> 3;
  const int lc = tid & 7;
  const uint32_t sw_off = (uint32_t)lr * 128 + (uint32_t)((lc ^ (lr & 7)) << 4);
  const __half* Wg = g_Wh + (size_t)(o0 + lr) * IN + lc * 8;
  const __half* Xg0 = g_Xh + ((size_t)bb * T + lr) * IN + lc * 8;

  // ---- mma per-thread constants ----
  const int warp_m = wid >> 1, warp_n = wid & 1;
  const int r = lane & 7;
  const int khA = lane >> 4;
  const int khB = (lane >> 3) & 1;
  const uint32_t aBase =
      (uint32_t)(warp_m * 64 + ((lane >> 3) & 1) * 8 + r) * 128;
  const uint32_t bBase =
      (uint32_t)(TT * 128) +
      (uint32_t)(warp_n * 64 + ((lane >> 4) << 3) + r) * 128;

  float acc[4][8][4];

  auto load_slab = [&](int g) {
    const int t0 = (g >> 4) * TT;
    const int k0 = (g & 15) * BKH;
    const uint32_t sb = sbase + (uint32_t)(g & 1) * STAGE_BYTES;
    const __half* Xg = Xg0 + (size_t)t0 * IN + k0;
    const __half* Ws = Wg + k0;
#pragma unroll
    for (int i = 0; i < 8; ++i)
      cp16(sb + sw_off + (uint32_t)i * 2048, Xg + (size_t)i * 16 * IN);
#pragma unroll
    for (int i = 0; i < 8; ++i)
      cp16(sb + (uint32_t)(TT * 128) + sw_off + (uint32_t)i * 2048,
           Ws + (size_t)i * 16 * IN);
  };

  // gate on tile 0 conversion (covers W too)
  if (tid == 0)
    while (!ld_acq(&g_flags[0])) __nanosleep(256);
  __syncthreads();

  int g = 0;
  load_slab(0);
  cp_commit();

  for (int tile = 0; tile < TILES; ++tile) {
#pragma unroll
    for (int mf = 0; mf < 4; ++mf)
#pragma unroll
      for (int nf = 0; nf < 8; ++nf)
#pragma unroll
        for (int j = 0; j < 4; ++j) acc[mf][nf][j] = 0.f;

    for (int ks = 0; ks < SLABS; ++ks) {
      cp_wait0();
      __syncthreads();
      if (g + 1 < G) {
        if (((g + 1) & 15) == 0) {  // next slab starts a new time-tile
          if (tid == 0)
            while (!ld_acq(&g_flags[(g + 1) >> 4])) __nanosleep(256);
          __syncthreads();
        }
        load_slab(g + 1);
        cp_commit();
      }
      const uint32_t sb = sbase + (uint32_t)(g & 1) * STAGE_BYTES;
#pragma unroll
      for (int kc = 0; kc < 4; ++kc) {
        uint32_t A[4][4], Bf[4][4];
        const uint32_t swA = (uint32_t)(((2 * kc + khA) ^ r) << 4);
        const uint32_t swB = (uint32_t)(((2 * kc + khB) ^ r) << 4);
#pragma unroll
        for (int mf = 0; mf < 4; ++mf)
          ldsm4(A[mf], sb + aBase + (uint32_t)mf * 2048 + swA);
#pragma unroll
        for (int p = 0; p < 4; ++p)
          ldsm4(Bf[p], sb + bBase + (uint32_t)p * 2048 + swB);
#pragma unroll
        for (int mf = 0; mf < 4; ++mf)
#pragma unroll
          for (int nf = 0; nf < 8; ++nf)
            mma16(acc[mf][nf], A[mf], &Bf[nf >> 1][(nf & 1) * 2]);
      }
      ++g;
    }

    // ---- epilogue: fragments -> fp16 staging [t][o] ----
    unsigned* stg_u = reinterpret_cast<unsigned*>(dsm + STAGING_OFF);
#pragma unroll
    for (int mf = 0; mf < 4; ++mf)
#pragma unroll
      for (int nf = 0; nf < 8; ++nf) {
        const int row = warp_m * 64 + mf * 16 + (lane >> 2);
        const int col = warp_n * 64 + nf * 8 + 2 * (lane & 3);
        stg_u[(row * STG_STRIDE + col) >> 1] =
            packh2(acc[mf][nf][0], acc[mf][nf][1]);
        stg_u[((row + 8) * STG_STRIDE + col) >> 1] =
            packh2(acc[mf][nf][2], acc[mf][nf][3]);
      }
    __syncthreads();

    // ---- fused leaky-integrator scan; carry u persists across tiles ----
    {
      const __half* sh = reinterpret_cast<const __half*>(dsm + STAGING_OFF);
      float* ob = out + ((size_t)bb * T + tile * TT) * OUT + o0 + tid;
#pragma unroll 8
      for (int t = 0; t < TT; ++t) {
        const float x = __half2float(sh[t * STG_STRIDE + tid]) + bo;
        u = fmaf(dcy, u, omd * x);
        ob[(size_t)t * OUT] = u;
      }
    }
  }
}

}  // namespace li

extern "C" void kernel_launch(void* const* d_in, const int* in_sizes, int n_in,
                              void* d_out, int out_size) {
  const float* X = (const float*)d_in[0];      // [B,T,IN]
  const float* W = (const float*)d_in[1];      // [OUT,IN]
  const float* bias = (const float*)d_in[2];   // [OUT]
  const float* decay = (const float*)d_in[3];  // [OUT]
  float* out = (float*)d_out;                  // [B,T,OUT]

  static cudaStream_t s2 = nullptr;
  static cudaEvent_t evF = nullptr, evJ = nullptr;
  static bool init = false;
  if (!init) {
    cudaFuncSetAttribute(li::li_kernel,
                         cudaFuncAttributeMaxDynamicSharedMemorySize,
                         li::SMEM_DYN);
    cudaStreamCreateWithFlags(&s2, cudaStreamNonBlocking);
    cudaEventCreateWithFlags(&evF, cudaEventDisableTiming);
    cudaEventCreateWithFlags(&evJ, cudaEventDisableTiming);
    init = true;
  }

  // reset device flags, then fork: cvt runs concurrently with the main kernel,
  // which gates each time-tile on the per-tile conversion flag.
  li::reset_kernel<<<1, 32>>>();
  cudaEventRecord(evF, 0);
  cudaStreamWaitEvent(s2, evF, 0);
  li::cvt_kernel<<<296, 256, 0, s2>>>((const float4*)X, (const float4*)W);
  li::li_kernel<<<li::B * (li::OUT / li::TO), 128, li::SMEM_DYN>>>(bias, decay,
                                                                   out);
  cudaEventRecord(evJ, s2);
  cudaStreamWaitEvent(0, evJ, 0);
}

// round 7
// speedup vs baseline: 1.0204x; 1.0204x over previous
#include <cuda_runtime.h>
#include <cuda_fp16.h>
#include <cstdint>
#include <cstddef>

#define DEVI static __device__ __forceinline__

namespace li {

constexpr int B = 32, T = 1024, IN = 1024, OUT = 1024;
constexpr int TT = 128;                 // time rows per tile (GEMM M)
constexpr int TO = 128;                 // out cols per CTA   (GEMM N)
constexpr int BKH = 64;                 // halves per K slab (= one 128B row)
constexpr int SLABS = IN / BKH;         // 16
constexpr int TILES = T / TT;           // 8
constexpr int G = TILES * SLABS;        // 128 slabs per CTA

constexpr int STAGE_BYTES = (TT + TO) * 128;   // 32 KB (X 16K + W 16K, fp16)
constexpr int STG_STRIDE = 136;                // halves; conflict-free
constexpr int STAGING_OFF = 2 * STAGE_BYTES;   // 65536
constexpr int SMEM_DYN = STAGING_OFF + TT * STG_STRIDE * 2;  // 100352

__device__ __align__(16) __half g_Xh[(size_t)B * T * IN];   // 64MB scratch
__device__ __align__(16) __half g_Wh[(size_t)OUT * IN];     // 2MB scratch
__device__ int g_xarr[B * TILES];   // per (batch,tile): 8 arrive + 8 consume, self-reset
__device__ int g_warr;              // W: 256 arrive + 256 consume, self-reset

DEVI uint32_t s2u(const void* p) {
  uint32_t a;
  asm("{ .reg .u64 t; cvta.to.shared.u64 t, %1; cvt.u32.u64 %0, t; }"
      : "=r"(a) : "l"(p));
  return a;
}
DEVI void cp16(uint32_t s, const void* g) {
  asm volatile("cp.async.cg.shared.global [%0], [%1], 16;" :: "r"(s), "l"(g)
               : "memory");
}
DEVI void cp_commit() { asm volatile("cp.async.commit_group;" ::: "memory"); }
DEVI void cp_wait0() { asm volatile("cp.async.wait_group 0;" ::: "memory"); }

DEVI void ldsm4(uint32_t* r, uint32_t a) {
  asm volatile("ldmatrix.sync.aligned.m8n8.x4.shared.b16 {%0,%1,%2,%3}, [%4];"
               : "=r"(r[0]), "=r"(r[1]), "=r"(r[2]), "=r"(r[3]) : "r"(a));
}
DEVI void mma16(float* c, const uint32_t* a, const uint32_t* b) {
  asm volatile(
      "mma.sync.aligned.m16n8k16.row.col.f32.f16.f16.f32 "
      "{%0,%1,%2,%3}, {%4,%5,%6,%7}, {%8,%9}, {%0,%1,%2,%3};"
      : "+f"(c[0]), "+f"(c[1]), "+f"(c[2]), "+f"(c[3])
      : "r"(a[0]), "r"(a[1]), "r"(a[2]), "r"(a[3]), "r"(b[0]), "r"(b[1]));
}
DEVI uint32_t packh2(float lo, float hi) {
  uint32_t d;
  asm("cvt.rn.f16x2.f32 %0, %1, %2;" : "=r"(d) : "f"(hi), "f"(lo));
  return d;
}
DEVI int ld_acq(const int* p) {
  int v;
  asm volatile("ld.acquire.gpu.global.b32 %0, [%1];" : "=r"(v) : "l"(p));
  return v;
}
DEVI int atom_add_rel(int* p, int v) {
  int o;
  asm volatile("atom.release.gpu.global.add.s32 %0, [%1], %2;"
               : "=r"(o) : "l"(p), "r"(v) : "memory");
  return o;
}
DEVI uint2 cvt2(float4 v) {
  __half2 a = __float22half2_rn({v.x, v.y});
  __half2 b = __float22half2_rn({v.z, v.w});
  uint2 u;
  u.x = *reinterpret_cast<unsigned*>(&a);
  u.y = *reinterpret_cast<unsigned*>(&b);
  return u;
}
// poll flag >= thresh, then consume; 2*thresh-th op resets to 0 for next replay
DEVI void wait_consume(int* f, int thresh, int tid) {
  if (tid == 0) {
    while (ld_acq(f) < thresh) __nanosleep(128);
    const int old = atomicAdd(f, 1);
    if (old == 2 * thresh - 1) atomicExch(f, 0);
  }
  __syncthreads();
}

// ---------------- single fused kernel: cvt + GEMM + leaky-integrator scan ----
// 128 threads, 4 warps in 2x2 grid, warp tile 64x64, 2 CTAs/SM (one wave).
__global__ void __launch_bounds__(128, 2)
li_kernel(const float4* __restrict__ Xf, const float4* __restrict__ Wf,
          const float* __restrict__ bias, const float* __restrict__ decay,
          float* __restrict__ out) {
  extern __shared__ __align__(16) char dsm[];
  const uint32_t sbase = s2u(dsm);

  const int tid = threadIdx.x;
  const int wid = tid >> 5;
  const int lane = tid & 31;
  const int bb = blockIdx.x >> 3;
  const int os = blockIdx.x & 7;
  const int o0 = os * TO;

  uint2* xo = reinterpret_cast<uint2*>(g_Xh);
  uint2* wo = reinterpret_cast<uint2*>(g_Wh);

  // ---- scan state: every thread owns one o-channel ----
  const float dcy = decay[o0 + tid];
  const float omd = 1.0f - dcy;
  const float bo = bias[o0 + tid];
  float u = 0.f;

  // ---------------- prologue: convert W share + X tile-0 share --------------
  {
    const int wbase = blockIdx.x * 1024;  // 1024 float4 of W per CTA
#pragma unroll
    for (int c = 0; c < 8; ++c) {
      const int j = wbase + c * 128 + tid;
      wo[j] = cvt2(Wf[j]);
    }
    // X share: rows [os*16, os*16+16) of tile 0 of batch bb = 4096 float4
    const size_t xbase = ((size_t)(bb * T + os * 16)) << 8;  // 256 f4 per row
#pragma unroll
    for (int c = 0; c < 32; ++c) {
      const size_t j = xbase + (size_t)(c >> 2) * 256 * 0 +  // rows interleaved below
                       (size_t)((c * 128 + tid) >> 8) * 256 +
                       (size_t)((c * 128 + tid) & 255);
      xo[j] = cvt2(Xf[j]);
    }
    __threadfence();
    __syncthreads();
    if (tid == 0) {
      atom_add_rel(&g_warr, 1);
      atom_add_rel(&g_xarr[bb * TILES], 1);
    }
    wait_consume(&g_warr, 256, tid);
    wait_consume(&g_xarr[bb * TILES], 8, tid);
  }

  // ---- cp.async constants: 16 chunks of 16B per thread ----
  const int lr = tid >> 3;
  const int lc = tid & 7;
  const uint32_t sw_off = (uint32_t)lr * 128 + (uint32_t)((lc ^ (lr & 7)) << 4);
  const __half* Wg = g_Wh + (size_t)(o0 + lr) * IN + lc * 8;
  const __half* Xg0 = g_Xh + ((size_t)bb * T + lr) * IN + lc * 8;

  // ---- mma per-thread constants ----
  const int warp_m = wid >> 1, warp_n = wid & 1;
  const int r = lane & 7;
  const int khA = lane >> 4;
  const int khB = (lane >> 3) & 1;
  const uint32_t aBase =
      (uint32_t)(warp_m * 64 + ((lane >> 3) & 1) * 8 + r) * 128;
  const uint32_t bBase =
      (uint32_t)(TT * 128) +
      (uint32_t)(warp_n * 64 + ((lane >> 4) << 3) + r) * 128;

  float acc[4][8][4];

  auto load_slab = [&](int g) {
    const int t0 = (g >> 4) * TT;
    const int k0 = (g & 15) * BKH;
    const uint32_t sb = sbase + (uint32_t)(g & 1) * STAGE_BYTES;
    const __half* Xg = Xg0 + (size_t)t0 * IN + k0;
    const __half* Ws = Wg + k0;
#pragma unroll
    for (int i = 0; i < 8; ++i)
      cp16(sb + sw_off + (uint32_t)i * 2048, Xg + (size_t)i * 16 * IN);
#pragma unroll
    for (int i = 0; i < 8; ++i)
      cp16(sb + (uint32_t)(TT * 128) + sw_off + (uint32_t)i * 2048,
           Ws + (size_t)i * 16 * IN);
  };

  int g = 0;
  load_slab(0);
  cp_commit();

  for (int tile = 0; tile < TILES; ++tile) {
#pragma unroll
    for (int mf = 0; mf < 4; ++mf)
#pragma unroll
      for (int nf = 0; nf < 8; ++nf)
#pragma unroll
        for (int j = 0; j < 4; ++j) acc[mf][nf][j] = 0.f;

    // base (in float4 units) of this CTA's conversion share of tile+1
    const size_t cvt_base =
        ((size_t)(bb * T + (tile + 1) * TT + os * 16)) << 8;

    for (int ks = 0; ks < SLABS; ++ks) {
      cp_wait0();
      __syncthreads();
      if (g + 1 < G) {
        if (((g + 1) & 15) == 0)  // next slab starts a new time-tile
          wait_consume(&g_xarr[bb * TILES + ((g + 1) >> 4)], 8, tid);
        load_slab(g + 1);
        cp_commit();
      }
      // ---- interleaved fp32->fp16 conversion of tile+1 (ks 0..7) ----
      if (tile + 1 < TILES) {
        if (ks < 8) {
#pragma unroll
          for (int q = 0; q < 4; ++q) {
            const int j = (ks * 4 + q) * 128 + tid;       // 0..4095
            const size_t idx =
                cvt_base + (size_t)(j >> 8) * 256 + (size_t)(j & 255);
            xo[idx] = cvt2(Xf[idx]);
          }
          if (ks == 7) __threadfence();
        } else if (ks == 8) {
          if (tid == 0) atom_add_rel(&g_xarr[bb * TILES + tile + 1], 1);
        }
      }

      const uint32_t sb = sbase + (uint32_t)(g & 1) * STAGE_BYTES;
#pragma unroll
      for (int kc = 0; kc < 4; ++kc) {
        uint32_t A[4][4], Bf[4][4];
        const uint32_t swA = (uint32_t)(((2 * kc + khA) ^ r) << 4);
        const uint32_t swB = (uint32_t)(((2 * kc + khB) ^ r) << 4);
#pragma unroll
        for (int mf = 0; mf < 4; ++mf)
          ldsm4(A[mf], sb + aBase + (uint32_t)mf * 2048 + swA);
#pragma unroll
        for (int p = 0; p < 4; ++p)
          ldsm4(Bf[p], sb + bBase + (uint32_t)p * 2048 + swB);
#pragma unroll
        for (int mf = 0; mf < 4; ++mf)
#pragma unroll
          for (int nf = 0; nf < 8; ++nf)
            mma16(acc[mf][nf], A[mf], &Bf[nf >> 1][(nf & 1) * 2]);
      }
      ++g;
    }

    // ---- epilogue: fragments -> fp16 staging [t][o] ----
    unsigned* stg_u = reinterpret_cast<unsigned*>(dsm + STAGING_OFF);
#pragma unroll
    for (int mf = 0; mf < 4; ++mf)
#pragma unroll
      for (int nf = 0; nf < 8; ++nf) {
        const int row = warp_m * 64 + mf * 16 + (lane >> 2);
        const int col = warp_n * 64 + nf * 8 + 2 * (lane & 3);
        stg_u[(row * STG_STRIDE + col) >> 1] =
            packh2(acc[mf][nf][0], acc[mf][nf][1]);
        stg_u[((row + 8) * STG_STRIDE + col) >> 1] =
            packh2(acc[mf][nf][2], acc[mf][nf][3]);
      }
    __syncthreads();

    // ---- fused leaky-integrator scan; carry u persists across tiles ----
    {
      const __half* sh = reinterpret_cast<const __half*>(dsm + STAGING_OFF);
      float* ob = out + ((size_t)bb * T + tile * TT) * OUT + o0 + tid;
#pragma unroll 8
      for (int t = 0; t < TT; ++t) {
        const float x = __half2float(sh[t * STG_STRIDE + tid]) + bo;
        u = fmaf(dcy, u, omd * x);
        ob[(size_t)t * OUT] = u;
      }
    }
  }
}

}  // namespace li

extern "C" void kernel_launch(void* const* d_in, const int* in_sizes, int n_in,
                              void* d_out, int out_size) {
  const float* X = (const float*)d_in[0];      // [B,T,IN]
  const float* W = (const float*)d_in[1];      // [OUT,IN]
  const float* bias = (const float*)d_in[2];   // [OUT]
  const float* decay = (const float*)d_in[3];  // [OUT]
  float* out = (float*)d_out;                  // [B,T,OUT]

  static bool init = false;
  if (!init) {
    cudaFuncSetAttribute(li::li_kernel,
                         cudaFuncAttributeMaxDynamicSharedMemorySize,
                         li::SMEM_DYN);
    init = true;
  }
  li::li_kernel<<<li::B * (li::OUT / li::TO), 128, li::SMEM_DYN>>>(
      (const float4*)X, (const float4*)W, bias, decay, out);
}